// round 15
// baseline (speedup 1.0000x reference)
#include <cuda_runtime.h>
#include <cuda_bf16.h>
#include <cstddef>
#include <cstdint>

#define S_LEN 2048
#define B_DIM 64
#define I_DIM 512
#define H_DIM 512
#define BH (B_DIM * H_DIM)          // 32768
#define GX_COLS 1024                // z gates [0,512), n gates [512,1024)
#define M_TOT ((size_t)S_LEN * B_DIM)   // 131072
#define Y1 384                      // m-tiles in GEMM part 1 (t < 768)

// Scratch: gx[t][b][g], g in 0..1023 maps to weight rows 512+g. 512 MB.
__device__ float g_gx[(size_t)S_LEN * B_DIM * GX_COLS];
// Pre-split bf16 operands (hi/lo error-compensated split).
__device__ __nv_bfloat16 g_xh[M_TOT * I_DIM];
__device__ __nv_bfloat16 g_xl[M_TOT * I_DIM];
__device__ __nv_bfloat16 g_wh[1024 * I_DIM];
__device__ __nv_bfloat16 g_wl[1024 * I_DIM];
// Per-m-tile gx readiness (8 n-CTAs each); zeroed by reset_rdy every launch.
__device__ int g_rdy[1024];
// Sense-reversing group barrier state (8 groups). Returns to {0,0} after the
// even number (2048) of flips each launch -> replay-safe.
__device__ int g_cnt[8];
__device__ int g_sense[8];

typedef unsigned long long ull;

__device__ __forceinline__ ull fma2(ull a, ull b, ull c) {
    ull d;
    asm("fma.rn.f32x2 %0, %1, %2, %3;" : "=l"(d) : "l"(a), "l"(b), "l"(c));
    return d;
}
__device__ __forceinline__ float sum2(ull u) {
    float lo, hi;
    asm("mov.b64 {%0,%1}, %2;" : "=f"(lo), "=f"(hi) : "l"(u));
    return lo + hi;
}
__device__ __forceinline__ void st_rel(int* p, int v) {
    asm volatile("st.release.gpu.global.b32 [%0], %1;" :: "l"(p), "r"(v) : "memory");
}
__device__ __forceinline__ int ld_acq(const int* p) {
    int v;
    asm volatile("ld.acquire.gpu.global.b32 %0, [%1];" : "=r"(v) : "l"(p) : "memory");
    return v;
}
__device__ __forceinline__ float fsig(float x) {
    return __fdividef(1.0f, 1.0f + __expf(-x));
}
__device__ __forceinline__ float ftanh(float x) {
    return 1.0f - __fdividef(2.0f, __expf(2.0f * x) + 1.0f);
}
__device__ __forceinline__ void split_bf16(float v, __nv_bfloat16& h, __nv_bfloat16& l) {
    h = __float2bfloat16_rn(v);
    l = __float2bfloat16_rn(v - __bfloat162float(h));
}
__device__ __forceinline__ void cp16(uint32_t saddr, const void* gaddr) {
    asm volatile("cp.async.cg.shared.global [%0], [%1], 16;"
                 :: "r"(saddr), "l"(gaddr));
}

// ---------------------------------------------------------------------------
// Pre-pass: fp32 -> bf16 hi/lo split. Each thread converts 8 elements.
// ---------------------------------------------------------------------------
__global__ void __launch_bounds__(256, 1)
conv_split(const float* __restrict__ src, __nv_bfloat16* __restrict__ dh,
           __nv_bfloat16* __restrict__ dl) {
    size_t i = ((size_t)blockIdx.x * 256 + threadIdx.x) * 8;
    float4 a = *(const float4*)(src + i);
    float4 b = *(const float4*)(src + i + 4);
    __nv_bfloat16 h[8], l[8];
    split_bf16(a.x, h[0], l[0]); split_bf16(a.y, h[1], l[1]);
    split_bf16(a.z, h[2], l[2]); split_bf16(a.w, h[3], l[3]);
    split_bf16(b.x, h[4], l[4]); split_bf16(b.y, h[5], l[5]);
    split_bf16(b.z, h[6], l[6]); split_bf16(b.w, h[7], l[7]);
    *(uint4*)(dh + i) = *(const uint4*)h;
    *(uint4*)(dl + i) = *(const uint4*)l;
}

__global__ void reset_rdy() {
    int i = blockIdx.x * 256 + threadIdx.x;
    if (i < 1024) g_rdy[i] = 0;
}

// ---------------------------------------------------------------------------
// Kernel 1: gx = x @ Wih[512:1536]^T + (bias_ih + bias_hh)[512:1536]
// EXACT R11 GEMM (bf16 hi/lo compensated, mma.m16n8k16, double-buffered
// cp.async, stride-20 conflict-free SMEM) + m-tile offset + ready flag.
// ---------------------------------------------------------------------------
__global__ void __launch_bounds__(256, 1)
gx_gemm(const float* __restrict__ bih, const float* __restrict__ bhh, int yoff) {
    __shared__ uint32_t SAH[2][128 * 20];
    __shared__ uint32_t SAL[2][128 * 20];
    __shared__ uint32_t SBH[2][128 * 20];
    __shared__ uint32_t SBL[2][128 * 20];

    const int tid = threadIdx.x;
    const int lane = tid & 31;
    const int wid = tid >> 5;
    const int wm = (wid & 3) * 32;
    const int wn = (wid >> 2) * 64;
    const int n0 = blockIdx.x * 128;
    const int ytile = blockIdx.y + yoff;
    const size_t m0 = (size_t)ytile * 128;

    const int row = tid >> 1;
    const int kh = tid & 1;
    const uint32_t soff = (uint32_t)(row * 20 + kh * 8) * 4;
    const __nv_bfloat16* axh = g_xh + (m0 + row) * I_DIM + kh * 16;
    const __nv_bfloat16* axl = g_xl + (m0 + row) * I_DIM + kh * 16;
    const __nv_bfloat16* bwh = g_wh + (size_t)(n0 + row) * I_DIM + kh * 16;
    const __nv_bfloat16* bwl = g_wl + (size_t)(n0 + row) * I_DIM + kh * 16;

    const uint32_t sAH0 = (uint32_t)__cvta_generic_to_shared(&SAH[0][0]);
    const uint32_t sAL0 = (uint32_t)__cvta_generic_to_shared(&SAL[0][0]);
    const uint32_t sBH0 = (uint32_t)__cvta_generic_to_shared(&SBH[0][0]);
    const uint32_t sBL0 = (uint32_t)__cvta_generic_to_shared(&SBL[0][0]);
    const uint32_t bufstride = 128 * 20 * 4;

    float acc[2][8][4];
#pragma unroll
    for (int mt = 0; mt < 2; mt++)
#pragma unroll
        for (int nt = 0; nt < 8; nt++)
#pragma unroll
            for (int i = 0; i < 4; i++) acc[mt][nt][i] = 0.f;

    auto issue_stage = [&](int s, int buf) {
        int ko = s * 32;
        uint32_t bo = buf * bufstride + soff;
        cp16(sAH0 + bo, axh + ko);
        cp16(sAH0 + bo + 16, axh + ko + 8);
        cp16(sAL0 + bo, axl + ko);
        cp16(sAL0 + bo + 16, axl + ko + 8);
        cp16(sBH0 + bo, bwh + ko);
        cp16(sBH0 + bo + 16, bwh + ko + 8);
        cp16(sBL0 + bo, bwl + ko);
        cp16(sBL0 + bo + 16, bwl + ko + 8);
        asm volatile("cp.async.commit_group;" ::: "memory");
    };

    issue_stage(0, 0);

    for (int s = 0; s < 16; s++) {
        const int buf = s & 1;
        if (s < 15) {
            issue_stage(s + 1, buf ^ 1);
            asm volatile("cp.async.wait_group 1;" ::: "memory");
        } else {
            asm volatile("cp.async.wait_group 0;" ::: "memory");
        }
        __syncthreads();

        const uint32_t* AH = &SAH[buf][0];
        const uint32_t* AL = &SAL[buf][0];
        const uint32_t* BBH = &SBH[buf][0];
        const uint32_t* BBL = &SBL[buf][0];

#pragma unroll
        for (int ks = 0; ks < 2; ks++) {
            const int ke = ks * 8 + (lane & 3);
            uint32_t ah[2][4], al[2][4];
#pragma unroll
            for (int mt = 0; mt < 2; mt++) {
                int r = wm + mt * 16 + (lane >> 2);
                ah[mt][0] = AH[r * 20 + ke];
                ah[mt][1] = AH[(r + 8) * 20 + ke];
                ah[mt][2] = AH[r * 20 + ke + 4];
                ah[mt][3] = AH[(r + 8) * 20 + ke + 4];
                al[mt][0] = AL[r * 20 + ke];
                al[mt][1] = AL[(r + 8) * 20 + ke];
                al[mt][2] = AL[r * 20 + ke + 4];
                al[mt][3] = AL[(r + 8) * 20 + ke + 4];
            }
#pragma unroll
            for (int nt = 0; nt < 8; nt++) {
                int nr = wn + nt * 8 + (lane >> 2);
                uint32_t bh0 = BBH[nr * 20 + ke];
                uint32_t bh1 = BBH[nr * 20 + ke + 4];
                uint32_t bl0 = BBL[nr * 20 + ke];
                uint32_t bl1 = BBL[nr * 20 + ke + 4];
#pragma unroll
                for (int mt = 0; mt < 2; mt++) {
                    float* c = acc[mt][nt];
                    asm("mma.sync.aligned.m16n8k16.row.col.f32.bf16.bf16.f32 "
                        "{%0,%1,%2,%3}, {%4,%5,%6,%7}, {%8,%9}, {%0,%1,%2,%3};"
                        : "+f"(c[0]), "+f"(c[1]), "+f"(c[2]), "+f"(c[3])
                        : "r"(ah[mt][0]), "r"(ah[mt][1]), "r"(ah[mt][2]), "r"(ah[mt][3]),
                          "r"(bh0), "r"(bh1));
                    asm("mma.sync.aligned.m16n8k16.row.col.f32.bf16.bf16.f32 "
                        "{%0,%1,%2,%3}, {%4,%5,%6,%7}, {%8,%9}, {%0,%1,%2,%3};"
                        : "+f"(c[0]), "+f"(c[1]), "+f"(c[2]), "+f"(c[3])
                        : "r"(ah[mt][0]), "r"(ah[mt][1]), "r"(ah[mt][2]), "r"(ah[mt][3]),
                          "r"(bl0), "r"(bl1));
                    asm("mma.sync.aligned.m16n8k16.row.col.f32.bf16.bf16.f32 "
                        "{%0,%1,%2,%3}, {%4,%5,%6,%7}, {%8,%9}, {%0,%1,%2,%3};"
                        : "+f"(c[0]), "+f"(c[1]), "+f"(c[2]), "+f"(c[3])
                        : "r"(al[mt][0]), "r"(al[mt][1]), "r"(al[mt][2]), "r"(al[mt][3]),
                          "r"(bh0), "r"(bh1));
                }
            }
        }
        __syncthreads();
    }

#pragma unroll
    for (int nt = 0; nt < 8; nt++) {
        int n = n0 + wn + nt * 8 + (lane & 3) * 2;
        float bz0 = bih[512 + n] + bhh[512 + n];
        float bz1 = bih[513 + n] + bhh[513 + n];
#pragma unroll
        for (int mt = 0; mt < 2; mt++) {
            size_t m = m0 + wm + mt * 16 + (lane >> 2);
            float* p0 = g_gx + m * GX_COLS + n;
            float* p1 = g_gx + (m + 8) * GX_COLS + n;
            *(float2*)p0 = make_float2(acc[mt][nt][0] + bz0, acc[mt][nt][1] + bz1);
            *(float2*)p1 = make_float2(acc[mt][nt][2] + bz0, acc[mt][nt][3] + bz1);
        }
    }

    // Publish readiness: all threads' stores -> fence -> bar -> one atomic.
    __threadfence();
    __syncthreads();
    if (tid == 0) atomicAdd(&g_rdy[ytile], 1);
}

// ---------------------------------------------------------------------------
// Kernel 2: recurrence — EXACT R7/R11 source (frozen), plus a guarded
// acquire-poll on gx readiness for t >= 768 (tiles produced by the
// concurrent GEMM part 2). Poll on even t only (one m-tile spans 2 steps).
// ---------------------------------------------------------------------------
__global__ void __launch_bounds__(256, 1)
rec_kernel(const float* __restrict__ h0, const float* __restrict__ whh,
           float* __restrict__ out) {
    __shared__ float4 h_s4[8][8][17];   // [b][q][kp] swizzled, k=(kp*8+q)*4+e

    const int tid = threadIdx.x;
    const int bx = blockIdx.x;
    const int grp = bx >> 4;
    const int gb = grp * 8;
    const int hd0 = (bx & 15) * 32;
    const int lane = tid & 31;
    const int wid = tid >> 5;
    const int kp = lane & 15;
    const int h1 = lane >> 4;
    const int hdg = wid * 2 + h1;
    const int hdp = hd0 + hdg * 2;
    const bool ep = (kp < 8);
    const int eb = kp;
    const int k4h = hdp >> 2;

    ulonglong2 wz0[8], wz1[8], wn0[8], wn1[8];
    {
        const ulonglong2* pz0 = (const ulonglong2*)(whh + (size_t)(512 + hdp) * 512 + kp * 32);
        const ulonglong2* pz1 = (const ulonglong2*)(whh + (size_t)(513 + hdp) * 512 + kp * 32);
        const ulonglong2* pn0 = (const ulonglong2*)(whh + (size_t)(1024 + hdp) * 512 + kp * 32);
        const ulonglong2* pn1 = (const ulonglong2*)(whh + (size_t)(1025 + hdp) * 512 + kp * 32);
#pragma unroll
        for (int q = 0; q < 8; q++) {
            wz0[q] = pz0[q];
            wz1[q] = pz1[q];
            wn0[q] = pn0[q];
            wn1[q] = pn1[q];
        }
    }

    {
        int b = tid >> 5, rr = tid & 31;
        const float4* src = (const float4*)(h0 + (size_t)(gb + b) * 512);
#pragma unroll
        for (int j = 0; j < 4; j++) {
            int k4 = j * 32 + rr;
            h_s4[b][k4 & 7][k4 >> 3] = __ldcg(src + k4);
        }
    }
    __syncthreads();

    int sense = 0;

    for (int t = 0; t < S_LEN; t++) {
        float2 pgz = make_float2(0.f, 0.f), pgn = make_float2(0.f, 0.f);
        if (ep) {
            // gx for t >= 768 is produced concurrently; wait for its m-tile.
            if (t >= 768 && (t & 1) == 0) {
                const int* rp = &g_rdy[t >> 1];
                while (ld_acq(rp) < 8) __nanosleep(64);
            }
            const float* gxt = g_gx + (size_t)t * B_DIM * GX_COLS + (size_t)(gb + eb) * GX_COLS;
            pgz = __ldcg((const float2*)(gxt + hdp));
            pgn = __ldcg((const float2*)(gxt + 512 + hdp));
        }

        float mz0 = 0.f, mz1 = 0.f, mn0 = 0.f, mn1 = 0.f;
#pragma unroll
        for (int b = 0; b < 8; b++) {
            ull az0 = 0, az1 = 0, an0 = 0, an1 = 0;
#pragma unroll
            for (int q = 0; q < 8; q++) {
                ulonglong2 h2 = *(const ulonglong2*)&h_s4[b][q][kp];
                az0 = fma2(wz0[q].x, h2.x, az0);
                az0 = fma2(wz0[q].y, h2.y, az0);
                az1 = fma2(wz1[q].x, h2.x, az1);
                az1 = fma2(wz1[q].y, h2.y, az1);
                an0 = fma2(wn0[q].x, h2.x, an0);
                an0 = fma2(wn0[q].y, h2.y, an0);
                an1 = fma2(wn1[q].x, h2.x, an1);
                an1 = fma2(wn1[q].y, h2.y, an1);
            }
            float rz0 = sum2(az0), rz1 = sum2(az1);
            float rn0 = sum2(an0), rn1 = sum2(an1);
#pragma unroll
            for (int off = 1; off < 16; off <<= 1) {
                rz0 += __shfl_xor_sync(0xffffffffu, rz0, off);
                rz1 += __shfl_xor_sync(0xffffffffu, rz1, off);
                rn0 += __shfl_xor_sync(0xffffffffu, rn0, off);
                rn1 += __shfl_xor_sync(0xffffffffu, rn1, off);
            }
            if (kp == b) { mz0 = rz0; mz1 = rz1; mn0 = rn0; mn1 = rn1; }
        }

        if (ep) {
            float4 ho4 = h_s4[eb][k4h & 7][k4h >> 3];
            float ho0 = (hdp & 2) ? ho4.z : ho4.x;
            float ho1 = (hdp & 2) ? ho4.w : ho4.y;
            float z0 = fsig(pgz.x + mz0);
            float z1 = fsig(pgz.y + mz1);
            float n0v = ftanh(pgn.x + mn0);
            float n1v = ftanh(pgn.y + mn1);
            float2 hv;
            hv.x = ho0 + z0 * (n0v - ho0);
            hv.y = ho1 + z1 * (n1v - ho1);
            float* dst = out + (size_t)t * BH + (size_t)(gb + eb) * 512 + hdp;
            *(float2*)dst = hv;
            if (t == S_LEN - 1) {
                float* dn = out + (size_t)S_LEN * BH + (size_t)(gb + eb) * 512 + hdp;
                *(float2*)dn = hv;
            }
        }

        __syncthreads();
        sense ^= 1;
        if (tid == 0) {
            asm volatile("fence.acq_rel.gpu;" ::: "memory");
            if (atomicAdd(&g_cnt[grp], 1) == 15) {
                g_cnt[grp] = 0;
                st_rel(&g_sense[grp], sense);
            } else {
                while (ld_acq(&g_sense[grp]) != sense) __nanosleep(32);
            }
        }
        __syncthreads();

        {
            int b = tid >> 5, rr = tid & 31;
            const float4* src = (const float4*)(out + (size_t)t * BH + (size_t)(gb + b) * 512);
#pragma unroll
            for (int j = 0; j < 4; j++) {
                int k4 = j * 32 + rr;
                h_s4[b][k4 & 7][k4 >> 3] = __ldcg(src + k4);
            }
        }
        __syncthreads();
    }
}

extern "C" void kernel_launch(void* const* d_in, const int* in_sizes, int n_in,
                              void* d_out, int out_size) {
    const float* x   = (const float*)d_in[0];  // (S, B, I)
    const float* h0  = (const float*)d_in[1];  // (1, B, H)
    const float* wih = (const float*)d_in[2];  // (3H, I)
    const float* whh = (const float*)d_in[3];  // (3H, H)
    const float* bih = (const float*)d_in[4];  // (3H,)
    const float* bhh = (const float*)d_in[5];  // (3H,)
    float* out = (float*)d_out;                // (1,S,B,H) then (1,B,H)

    __nv_bfloat16 *xh, *xl, *wh, *wl;
    cudaGetSymbolAddress((void**)&xh, g_xh);
    cudaGetSymbolAddress((void**)&xl, g_xl);
    cudaGetSymbolAddress((void**)&wh, g_wh);
    cudaGetSymbolAddress((void**)&wl, g_wl);

    // Side stream + fork/join events for the overlapped branch. Created once
    // (host-side resources only); first call is the uncaptured correctness
    // run, so creation never happens inside graph capture.
    static cudaStream_t s2 = nullptr;
    static cudaEvent_t evF = nullptr, evJ = nullptr;
    static bool tried = false;
    if (!tried) {
        tried = true;
        if (cudaStreamCreateWithFlags(&s2, cudaStreamNonBlocking) != cudaSuccess)
            s2 = nullptr;
        if (s2 &&
            (cudaEventCreateWithFlags(&evF, cudaEventDisableTiming) != cudaSuccess ||
             cudaEventCreateWithFlags(&evJ, cudaEventDisableTiming) != cudaSuccess))
            s2 = nullptr;
        cudaGetLastError();
    }

    // Stream 0: conv -> flag reset -> GEMM part 1 (t < 768).
    conv_split<<<32768, 256>>>(x, xh, xl);
    conv_split<<<256, 256>>>(wih + (size_t)512 * I_DIM, wh, wl);
    reset_rdy<<<4, 256>>>();
    gx_gemm<<<dim3(8, Y1), 256>>>(bih, bhh, 0);

    if (s2) {
        // Fork: rec on stream 0 runs CONCURRENTLY with GEMM part 2 on s2.
        cudaEventRecord(evF, 0);
        cudaStreamWaitEvent(s2, evF, 0);
        rec_kernel<<<128, 256>>>(h0, whh, out);
        gx_gemm<<<dim3(8, 1024 - Y1), 256, 0, s2>>>(bih, bhh, Y1);
        cudaEventRecord(evJ, s2);
        cudaStreamWaitEvent(0, evJ, 0);
    } else {
        // Sequential fallback (== R11 behavior; flags all ready before rec).
        gx_gemm<<<dim3(8, 1024 - Y1), 256>>>(bih, bhh, Y1);
        rec_kernel<<<128, 256>>>(h0, whh, out);
    }
}

// round 16
// speedup vs baseline: 1.5274x; 1.5274x over previous
#include <cuda_runtime.h>
#include <cuda_bf16.h>
#include <cstddef>
#include <cstdint>

#define S_LEN 2048
#define B_DIM 64
#define I_DIM 512
#define H_DIM 512
#define BH (B_DIM * H_DIM)          // 32768
#define GX_COLS 1024                // z gates [0,512), n gates [512,1024)
#define M_TOT ((size_t)S_LEN * B_DIM)   // 131072

// Scratch: gx[t][b][g], g in 0..1023 maps to weight rows 512+g. 512 MB.
__device__ float g_gx[(size_t)S_LEN * B_DIM * GX_COLS];
// Pre-split bf16 operands (hi/lo error-compensated split).
__device__ __nv_bfloat16 g_xh[M_TOT * I_DIM];
__device__ __nv_bfloat16 g_xl[M_TOT * I_DIM];
__device__ __nv_bfloat16 g_wh[1024 * I_DIM];
__device__ __nv_bfloat16 g_wl[1024 * I_DIM];
// Sense-reversing group barrier state (8 groups). Returns to {0,0} after the
// even number (2048) of flips each launch -> replay-safe.
__device__ int g_cnt[8];
__device__ int g_sense[8];

typedef unsigned long long ull;

__device__ __forceinline__ ull fma2(ull a, ull b, ull c) {
    ull d;
    asm("fma.rn.f32x2 %0, %1, %2, %3;" : "=l"(d) : "l"(a), "l"(b), "l"(c));
    return d;
}
__device__ __forceinline__ float sum2(ull u) {
    float lo, hi;
    asm("mov.b64 {%0,%1}, %2;" : "=f"(lo), "=f"(hi) : "l"(u));
    return lo + hi;
}
__device__ __forceinline__ void st_rel(int* p, int v) {
    asm volatile("st.release.gpu.global.b32 [%0], %1;" :: "l"(p), "r"(v) : "memory");
}
__device__ __forceinline__ int ld_acq(const int* p) {
    int v;
    asm volatile("ld.acquire.gpu.global.b32 %0, [%1];" : "=r"(v) : "l"(p) : "memory");
    return v;
}
__device__ __forceinline__ float fsig(float x) {
    return __fdividef(1.0f, 1.0f + __expf(-x));
}
__device__ __forceinline__ float ftanh(float x) {
    return 1.0f - __fdividef(2.0f, __expf(2.0f * x) + 1.0f);
}
__device__ __forceinline__ void split_bf16(float v, __nv_bfloat16& h, __nv_bfloat16& l) {
    h = __float2bfloat16_rn(v);
    l = __float2bfloat16_rn(v - __bfloat162float(h));
}
__device__ __forceinline__ void cp16(uint32_t saddr, const void* gaddr) {
    asm volatile("cp.async.cg.shared.global [%0], [%1], 16;"
                 :: "r"(saddr), "l"(gaddr));
}
__device__ __forceinline__ void ldsm4(uint32_t addr, uint32_t* r) {
    asm volatile("ldmatrix.sync.aligned.m8n8.x4.shared.b16 {%0,%1,%2,%3}, [%4];"
                 : "=r"(r[0]), "=r"(r[1]), "=r"(r[2]), "=r"(r[3]) : "r"(addr));
}

// ---------------------------------------------------------------------------
// Pre-pass: fp32 -> bf16 hi/lo split. Each thread converts 8 elements.
// ---------------------------------------------------------------------------
__global__ void __launch_bounds__(256, 1)
conv_split(const float* __restrict__ src, __nv_bfloat16* __restrict__ dh,
           __nv_bfloat16* __restrict__ dl) {
    size_t i = ((size_t)blockIdx.x * 256 + threadIdx.x) * 8;
    float4 a = *(const float4*)(src + i);
    float4 b = *(const float4*)(src + i + 4);
    __nv_bfloat16 h[8], l[8];
    split_bf16(a.x, h[0], l[0]); split_bf16(a.y, h[1], l[1]);
    split_bf16(a.z, h[2], l[2]); split_bf16(a.w, h[3], l[3]);
    split_bf16(b.x, h[4], l[4]); split_bf16(b.y, h[5], l[5]);
    split_bf16(b.z, h[6], l[6]); split_bf16(b.w, h[7], l[7]);
    *(uint4*)(dh + i) = *(const uint4*)h;
    *(uint4*)(dl + i) = *(const uint4*)l;
}

// ---------------------------------------------------------------------------
// Kernel 1: gx = x @ Wih[512:1536]^T + (bias_ih + bias_hh)[512:1536]
// R11 structure (bf16 hi/lo compensated, mma.m16n8k16, double-buffered
// cp.async, stride-20 SMEM) with fragment loads via ldmatrix.m8n8.x4
// (conflict-free at stride 20: 8 rows hit banks {0,20,8,28,16,4,24,12}+c)
// and 2 CTAs/SM. Fragment bits identical to R11 -> identical numerics.
// ---------------------------------------------------------------------------
__global__ void __launch_bounds__(256, 2)
gx_gemm(const float* __restrict__ bih, const float* __restrict__ bhh) {
    __shared__ uint32_t SAH[2][128 * 20];
    __shared__ uint32_t SAL[2][128 * 20];
    __shared__ uint32_t SBH[2][128 * 20];
    __shared__ uint32_t SBL[2][128 * 20];

    const int tid = threadIdx.x;
    const int lane = tid & 31;
    const int wid = tid >> 5;
    const int wm = (wid & 3) * 32;
    const int wn = (wid >> 2) * 64;
    const int n0 = blockIdx.x * 128;
    const size_t m0 = (size_t)blockIdx.y * 128;

    // Staging: row r = tid>>1, k-half kh = tid&1 (16 bf16 = 32B = 2 chunks).
    const int row = tid >> 1;
    const int kh = tid & 1;
    const uint32_t soff = (uint32_t)(row * 20 + kh * 8) * 4;
    const __nv_bfloat16* axh = g_xh + (m0 + row) * I_DIM + kh * 16;
    const __nv_bfloat16* axl = g_xl + (m0 + row) * I_DIM + kh * 16;
    const __nv_bfloat16* bwh = g_wh + (size_t)(n0 + row) * I_DIM + kh * 16;
    const __nv_bfloat16* bwl = g_wl + (size_t)(n0 + row) * I_DIM + kh * 16;

    const uint32_t sAH0 = (uint32_t)__cvta_generic_to_shared(&SAH[0][0]);
    const uint32_t sAL0 = (uint32_t)__cvta_generic_to_shared(&SAL[0][0]);
    const uint32_t sBH0 = (uint32_t)__cvta_generic_to_shared(&SBH[0][0]);
    const uint32_t sBL0 = (uint32_t)__cvta_generic_to_shared(&SBL[0][0]);
    const uint32_t bufstride = 128 * 20 * 4;

    // ldmatrix per-lane addressing. quad q = lane>>3.
    // A (x4 regs = rows0-7@c0, rows8-15@c0, rows0-7@c4, rows8-15@c4):
    //   row_off = (q&1)*8 + (lane&7), col_off = (q>>1)*4.
    // B (x4 regs = bh0(nt), bh1(nt), bh0(nt+1), bh1(nt+1)):
    //   row_off = (q>>1)*8 + (lane&7), col_off = (q&1)*4.
    const int q = lane >> 3;
    const int l7 = lane & 7;
    const uint32_t aoff = (uint32_t)(((wm + (q & 1) * 8 + l7) * 20 + (q >> 1) * 4) * 4);
    const uint32_t boff = (uint32_t)(((wn + (q >> 1) * 8 + l7) * 20 + (q & 1) * 4) * 4);

    float acc[2][8][4];
#pragma unroll
    for (int mt = 0; mt < 2; mt++)
#pragma unroll
        for (int nt = 0; nt < 8; nt++)
#pragma unroll
            for (int i = 0; i < 4; i++) acc[mt][nt][i] = 0.f;

    auto issue_stage = [&](int s, int buf) {
        int ko = s * 32;
        uint32_t bo = buf * bufstride + soff;
        cp16(sAH0 + bo, axh + ko);
        cp16(sAH0 + bo + 16, axh + ko + 8);
        cp16(sAL0 + bo, axl + ko);
        cp16(sAL0 + bo + 16, axl + ko + 8);
        cp16(sBH0 + bo, bwh + ko);
        cp16(sBH0 + bo + 16, bwh + ko + 8);
        cp16(sBL0 + bo, bwl + ko);
        cp16(sBL0 + bo + 16, bwl + ko + 8);
        asm volatile("cp.async.commit_group;" ::: "memory");
    };

    issue_stage(0, 0);

    for (int s = 0; s < 16; s++) {
        const int buf = s & 1;
        if (s < 15) {
            issue_stage(s + 1, buf ^ 1);
            asm volatile("cp.async.wait_group 1;" ::: "memory");
        } else {
            asm volatile("cp.async.wait_group 0;" ::: "memory");
        }
        __syncthreads();

        const uint32_t bb = buf * bufstride;

#pragma unroll
        for (int ks = 0; ks < 2; ks++) {
            const uint32_t kso = ks * 32;           // ks*8 u32 = 32 bytes
            uint32_t ah[2][4], al[2][4];
#pragma unroll
            for (int mt = 0; mt < 2; mt++) {
                const uint32_t mo = mt * (16 * 20 * 4);
                ldsm4(sAH0 + bb + aoff + mo + kso, ah[mt]);
                ldsm4(sAL0 + bb + aoff + mo + kso, al[mt]);
            }
#pragma unroll
            for (int ntp = 0; ntp < 4; ntp++) {
                const uint32_t no = ntp * (16 * 20 * 4);
                uint32_t bh[4], bl[4];
                ldsm4(sBH0 + bb + boff + no + kso, bh);
                ldsm4(sBL0 + bb + boff + no + kso, bl);
#pragma unroll
                for (int sub = 0; sub < 2; sub++) {
                    const int nt = ntp * 2 + sub;
                    const uint32_t bh0 = bh[sub * 2], bh1 = bh[sub * 2 + 1];
                    const uint32_t bl0 = bl[sub * 2], bl1 = bl[sub * 2 + 1];
#pragma unroll
                    for (int mt = 0; mt < 2; mt++) {
                        float* c = acc[mt][nt];
                        asm("mma.sync.aligned.m16n8k16.row.col.f32.bf16.bf16.f32 "
                            "{%0,%1,%2,%3}, {%4,%5,%6,%7}, {%8,%9}, {%0,%1,%2,%3};"
                            : "+f"(c[0]), "+f"(c[1]), "+f"(c[2]), "+f"(c[3])
                            : "r"(ah[mt][0]), "r"(ah[mt][1]), "r"(ah[mt][2]), "r"(ah[mt][3]),
                              "r"(bh0), "r"(bh1));
                        asm("mma.sync.aligned.m16n8k16.row.col.f32.bf16.bf16.f32 "
                            "{%0,%1,%2,%3}, {%4,%5,%6,%7}, {%8,%9}, {%0,%1,%2,%3};"
                            : "+f"(c[0]), "+f"(c[1]), "+f"(c[2]), "+f"(c[3])
                            : "r"(ah[mt][0]), "r"(ah[mt][1]), "r"(ah[mt][2]), "r"(ah[mt][3]),
                              "r"(bl0), "r"(bl1));
                        asm("mma.sync.aligned.m16n8k16.row.col.f32.bf16.bf16.f32 "
                            "{%0,%1,%2,%3}, {%4,%5,%6,%7}, {%8,%9}, {%0,%1,%2,%3};"
                            : "+f"(c[0]), "+f"(c[1]), "+f"(c[2]), "+f"(c[3])
                            : "r"(al[mt][0]), "r"(al[mt][1]), "r"(al[mt][2]), "r"(al[mt][3]),
                              "r"(bh0), "r"(bh1));
                    }
                }
            }
        }
        __syncthreads();
    }

    // Epilogue: rows m0+wm+mt*16+(lane>>2) (+8), cols n0+wn+nt*8+(lane&3)*2.
#pragma unroll
    for (int nt = 0; nt < 8; nt++) {
        int n = n0 + wn + nt * 8 + (lane & 3) * 2;
        float bz0 = bih[512 + n] + bhh[512 + n];
        float bz1 = bih[513 + n] + bhh[513 + n];
#pragma unroll
        for (int mt = 0; mt < 2; mt++) {
            size_t m = m0 + wm + mt * 16 + (lane >> 2);
            float* p0 = g_gx + m * GX_COLS + n;
            float* p1 = g_gx + (m + 8) * GX_COLS + n;
            *(float2*)p0 = make_float2(acc[mt][nt][0] + bz0, acc[mt][nt][1] + bz1);
            *(float2*)p1 = make_float2(acc[mt][nt][2] + bz0, acc[mt][nt][3] + bz1);
        }
    }
}

// ---------------------------------------------------------------------------
// Kernel 2: recurrence — EXACT R7/R11 source (frozen; best measured).
// ---------------------------------------------------------------------------
__global__ void __launch_bounds__(256, 1)
rec_kernel(const float* __restrict__ h0, const float* __restrict__ whh,
           float* __restrict__ out) {
    __shared__ float4 h_s4[8][8][17];   // [b][q][kp] swizzled, k=(kp*8+q)*4+e

    const int tid = threadIdx.x;
    const int bx = blockIdx.x;
    const int grp = bx >> 4;
    const int gb = grp * 8;
    const int hd0 = (bx & 15) * 32;
    const int lane = tid & 31;
    const int wid = tid >> 5;
    const int kp = lane & 15;
    const int h1 = lane >> 4;
    const int hdg = wid * 2 + h1;
    const int hdp = hd0 + hdg * 2;
    const bool ep = (kp < 8);
    const int eb = kp;
    const int k4h = hdp >> 2;

    ulonglong2 wz0[8], wz1[8], wn0[8], wn1[8];
    {
        const ulonglong2* pz0 = (const ulonglong2*)(whh + (size_t)(512 + hdp) * 512 + kp * 32);
        const ulonglong2* pz1 = (const ulonglong2*)(whh + (size_t)(513 + hdp) * 512 + kp * 32);
        const ulonglong2* pn0 = (const ulonglong2*)(whh + (size_t)(1024 + hdp) * 512 + kp * 32);
        const ulonglong2* pn1 = (const ulonglong2*)(whh + (size_t)(1025 + hdp) * 512 + kp * 32);
#pragma unroll
        for (int qq = 0; qq < 8; qq++) {
            wz0[qq] = pz0[qq];
            wz1[qq] = pz1[qq];
            wn0[qq] = pn0[qq];
            wn1[qq] = pn1[qq];
        }
    }

    {
        int b = tid >> 5, rr = tid & 31;
        const float4* src = (const float4*)(h0 + (size_t)(gb + b) * 512);
#pragma unroll
        for (int j = 0; j < 4; j++) {
            int k4 = j * 32 + rr;
            h_s4[b][k4 & 7][k4 >> 3] = __ldcg(src + k4);
        }
    }
    __syncthreads();

    int sense = 0;

    for (int t = 0; t < S_LEN; t++) {
        float2 pgz = make_float2(0.f, 0.f), pgn = make_float2(0.f, 0.f);
        if (ep) {
            const float* gxt = g_gx + (size_t)t * B_DIM * GX_COLS + (size_t)(gb + eb) * GX_COLS;
            pgz = __ldcg((const float2*)(gxt + hdp));
            pgn = __ldcg((const float2*)(gxt + 512 + hdp));
        }

        float mz0 = 0.f, mz1 = 0.f, mn0 = 0.f, mn1 = 0.f;
#pragma unroll
        for (int b = 0; b < 8; b++) {
            ull az0 = 0, az1 = 0, an0 = 0, an1 = 0;
#pragma unroll
            for (int qq = 0; qq < 8; qq++) {
                ulonglong2 h2 = *(const ulonglong2*)&h_s4[b][qq][kp];
                az0 = fma2(wz0[qq].x, h2.x, az0);
                az0 = fma2(wz0[qq].y, h2.y, az0);
                az1 = fma2(wz1[qq].x, h2.x, az1);
                az1 = fma2(wz1[qq].y, h2.y, az1);
                an0 = fma2(wn0[qq].x, h2.x, an0);
                an0 = fma2(wn0[qq].y, h2.y, an0);
                an1 = fma2(wn1[qq].x, h2.x, an1);
                an1 = fma2(wn1[qq].y, h2.y, an1);
            }
            float rz0 = sum2(az0), rz1 = sum2(az1);
            float rn0 = sum2(an0), rn1 = sum2(an1);
#pragma unroll
            for (int off = 1; off < 16; off <<= 1) {
                rz0 += __shfl_xor_sync(0xffffffffu, rz0, off);
                rz1 += __shfl_xor_sync(0xffffffffu, rz1, off);
                rn0 += __shfl_xor_sync(0xffffffffu, rn0, off);
                rn1 += __shfl_xor_sync(0xffffffffu, rn1, off);
            }
            if (kp == b) { mz0 = rz0; mz1 = rz1; mn0 = rn0; mn1 = rn1; }
        }

        if (ep) {
            float4 ho4 = h_s4[eb][k4h & 7][k4h >> 3];
            float ho0 = (hdp & 2) ? ho4.z : ho4.x;
            float ho1 = (hdp & 2) ? ho4.w : ho4.y;
            float z0 = fsig(pgz.x + mz0);
            float z1 = fsig(pgz.y + mz1);
            float n0v = ftanh(pgn.x + mn0);
            float n1v = ftanh(pgn.y + mn1);
            float2 hv;
            hv.x = ho0 + z0 * (n0v - ho0);
            hv.y = ho1 + z1 * (n1v - ho1);
            float* dst = out + (size_t)t * BH + (size_t)(gb + eb) * 512 + hdp;
            *(float2*)dst = hv;
            if (t == S_LEN - 1) {
                float* dn = out + (size_t)S_LEN * BH + (size_t)(gb + eb) * 512 + hdp;
                *(float2*)dn = hv;
            }
        }

        __syncthreads();
        sense ^= 1;
        if (tid == 0) {
            asm volatile("fence.acq_rel.gpu;" ::: "memory");
            if (atomicAdd(&g_cnt[grp], 1) == 15) {
                g_cnt[grp] = 0;
                st_rel(&g_sense[grp], sense);
            } else {
                while (ld_acq(&g_sense[grp]) != sense) __nanosleep(32);
            }
        }
        __syncthreads();

        {
            int b = tid >> 5, rr = tid & 31;
            const float4* src = (const float4*)(out + (size_t)t * BH + (size_t)(gb + b) * 512);
#pragma unroll
            for (int j = 0; j < 4; j++) {
                int k4 = j * 32 + rr;
                h_s4[b][k4 & 7][k4 >> 3] = __ldcg(src + k4);
            }
        }
        __syncthreads();
    }
}

extern "C" void kernel_launch(void* const* d_in, const int* in_sizes, int n_in,
                              void* d_out, int out_size) {
    const float* x   = (const float*)d_in[0];  // (S, B, I)
    const float* h0  = (const float*)d_in[1];  // (1, B, H)
    const float* wih = (const float*)d_in[2];  // (3H, I)
    const float* whh = (const float*)d_in[3];  // (3H, H)
    const float* bih = (const float*)d_in[4];  // (3H,)
    const float* bhh = (const float*)d_in[5];  // (3H,)
    float* out = (float*)d_out;                // (1,S,B,H) then (1,B,H)

    __nv_bfloat16 *xh, *xl, *wh, *wl;
    cudaGetSymbolAddress((void**)&xh, g_xh);
    cudaGetSymbolAddress((void**)&xl, g_xl);
    cudaGetSymbolAddress((void**)&wh, g_wh);
    cudaGetSymbolAddress((void**)&wl, g_wl);

    // Pre-split x and Wih rows 512..1535.
    conv_split<<<32768, 256>>>(x, xh, xl);
    conv_split<<<256, 256>>>(wih + (size_t)512 * I_DIM, wh, wl);

    dim3 ggrid(8, 1024);                       // N-tiles x M-tiles
    gx_gemm<<<ggrid, 256>>>(bih, bhh);
    rec_kernel<<<128, 256>>>(h0, whh, out);
}